// round 3
// baseline (speedup 1.0000x reference)
#include <cuda_runtime.h>
#include <cuda_bf16.h>

#define D 128
#define NN 50000
#define NS 20000
#define NE 600000
#define ES 120000

// Scratch (alloc guards forbid cudaMalloc; __device__ globals are the sanctioned path)
__device__ float g_agg[(size_t)NN * D];   // agg / msg (reused)
__device__ float g_h  [(size_t)NN * D];   // x after relu
__device__ float g_h1 [(size_t)NN * D];   // after level 0
__device__ float g_sub [(size_t)NS * D];
__device__ float g_sub2[(size_t)NS * D];

// ---------------------------------------------------------------------------
// Edge scatter: out[sidx[e]] += feat[gidx[e]]   (warp per edge, v4 reductions)
// indices are int32 (JAX x64-disabled downgrades int64 -> int32)
// ---------------------------------------------------------------------------
__global__ void scatter_add_k(const float* __restrict__ feat,
                              const int* __restrict__ gidx,
                              const int* __restrict__ sidx,
                              float* __restrict__ out, int nE)
{
    int t = blockIdx.x * blockDim.x + threadIdx.x;
    int e = t >> 5;
    int lane = t & 31;
    if (e >= nE) return;
    int g = gidx[e];
    int s = sidx[e];
    float4 v = reinterpret_cast<const float4*>(feat + (size_t)g * D)[lane];
    float* dst = out + (size_t)s * D + lane * 4;
    asm volatile("red.global.add.v4.f32 [%0], {%1,%2,%3,%4};"
                 :: "l"(dst), "f"(v.x), "f"(v.y), "f"(v.z), "f"(v.w)
                 : "memory");
}

// ---------------------------------------------------------------------------
// 3xTF32 tensor-core GEMM: y[M,128] = epi( (A (+A2)) @ W + bias (+res) )
// Block tile 64x128, 8 warps (2x4), warp tile 32x32 via m16n8k8 tf32 mma.
// Precision: operands split hi/lo (tf32), acc += lo*hi + hi*lo + hi*hi.
// ---------------------------------------------------------------------------
__device__ __forceinline__ void tf32_split(float x, unsigned& hi, unsigned& lo)
{
    asm("cvt.rna.tf32.f32 %0, %1;" : "=r"(hi) : "f"(x));
    float r = x - __uint_as_float(hi);
    asm("cvt.rna.tf32.f32 %0, %1;" : "=r"(lo) : "f"(r));
}

__device__ __forceinline__ void mma8(float c[4], const unsigned a[4], const unsigned b[2])
{
    asm volatile(
        "mma.sync.aligned.m16n8k8.row.col.f32.tf32.tf32.f32 "
        "{%0,%1,%2,%3}, {%4,%5,%6,%7}, {%8,%9}, {%0,%1,%2,%3};"
        : "+f"(c[0]), "+f"(c[1]), "+f"(c[2]), "+f"(c[3])
        : "r"(a[0]), "r"(a[1]), "r"(a[2]), "r"(a[3]), "r"(b[0]), "r"(b[1]));
}

template<bool RELU, bool HAS_IN2, bool HAS_RES>
__global__ __launch_bounds__(256)
void gemm128_tc(const float* __restrict__ A, const float* __restrict__ A2,
                const float* __restrict__ W, const float* __restrict__ bias,
                const float* __restrict__ res, float* __restrict__ out, int M)
{
    __shared__ unsigned As_hi[64][17], As_lo[64][17];
    __shared__ unsigned Ws_hi[16][132], Ws_lo[16][132];

    const int tid   = threadIdx.x;
    const int lane  = tid & 31;
    const int wid   = tid >> 5;
    const int warp_m = wid & 1;          // 0..1  (32 rows each)
    const int warp_n = wid >> 1;         // 0..3  (32 cols each)
    const int grp   = lane >> 2;         // 0..7
    const int tig   = lane & 3;          // 0..3
    const int row0  = blockIdx.x * 64;

    float acc[2][4][4];
    #pragma unroll
    for (int i = 0; i < 2; i++)
        #pragma unroll
        for (int j = 0; j < 4; j++)
            #pragma unroll
            for (int c = 0; c < 4; c++) acc[i][j][c] = 0.f;

    for (int k0 = 0; k0 < 128; k0 += 16) {
        // --- stage A tile (64x16): load fp32, add A2, split to hi/lo in smem ---
        {
            int e = tid * 4;
            int r = e >> 4, k = e & 15;
            int grow = row0 + r;
            float4 v = make_float4(0.f, 0.f, 0.f, 0.f);
            if (grow < M) {
                v = *reinterpret_cast<const float4*>(A + (size_t)grow * 128 + k0 + k);
                if (HAS_IN2) {
                    float4 u = *reinterpret_cast<const float4*>(A2 + (size_t)grow * 128 + k0 + k);
                    v.x += u.x; v.y += u.y; v.z += u.z; v.w += u.w;
                }
            }
            unsigned hi, lo;
            tf32_split(v.x, hi, lo); As_hi[r][k+0] = hi; As_lo[r][k+0] = lo;
            tf32_split(v.y, hi, lo); As_hi[r][k+1] = hi; As_lo[r][k+1] = lo;
            tf32_split(v.z, hi, lo); As_hi[r][k+2] = hi; As_lo[r][k+2] = lo;
            tf32_split(v.w, hi, lo); As_hi[r][k+3] = hi; As_lo[r][k+3] = lo;
        }
        // --- stage W tile (16x128): split to hi/lo ---
        #pragma unroll
        for (int h = 0; h < 2; h++) {
            int e = tid * 4 + h * 1024;
            int kk = e >> 7, j = e & 127;
            float4 v = *reinterpret_cast<const float4*>(W + (size_t)(k0 + kk) * 128 + j);
            unsigned hi, lo;
            tf32_split(v.x, hi, lo); Ws_hi[kk][j+0] = hi; Ws_lo[kk][j+0] = lo;
            tf32_split(v.y, hi, lo); Ws_hi[kk][j+1] = hi; Ws_lo[kk][j+1] = lo;
            tf32_split(v.z, hi, lo); Ws_hi[kk][j+2] = hi; Ws_lo[kk][j+2] = lo;
            tf32_split(v.w, hi, lo); Ws_hi[kk][j+3] = hi; Ws_lo[kk][j+3] = lo;
        }
        __syncthreads();

        #pragma unroll
        for (int kk = 0; kk < 16; kk += 8) {
            // A fragments (2 m-atoms)
            unsigned ah[2][4], al[2][4];
            #pragma unroll
            for (int i = 0; i < 2; i++) {
                int r = warp_m * 32 + i * 16 + grp;
                ah[i][0] = As_hi[r    ][kk + tig    ];  al[i][0] = As_lo[r    ][kk + tig    ];
                ah[i][1] = As_hi[r + 8][kk + tig    ];  al[i][1] = As_lo[r + 8][kk + tig    ];
                ah[i][2] = As_hi[r    ][kk + tig + 4];  al[i][2] = As_lo[r    ][kk + tig + 4];
                ah[i][3] = As_hi[r + 8][kk + tig + 4];  al[i][3] = As_lo[r + 8][kk + tig + 4];
            }
            // B fragments (4 n-atoms)
            unsigned bh[4][2], bl[4][2];
            #pragma unroll
            for (int j = 0; j < 4; j++) {
                int c = warp_n * 32 + j * 8 + grp;
                bh[j][0] = Ws_hi[kk + tig    ][c];  bl[j][0] = Ws_lo[kk + tig    ][c];
                bh[j][1] = Ws_hi[kk + tig + 4][c];  bl[j][1] = Ws_lo[kk + tig + 4][c];
            }
            #pragma unroll
            for (int i = 0; i < 2; i++)
                #pragma unroll
                for (int j = 0; j < 4; j++) {
                    mma8(acc[i][j], al[i], bh[j]);   // lo*hi
                    mma8(acc[i][j], ah[i], bl[j]);   // hi*lo
                    mma8(acc[i][j], ah[i], bh[j]);   // hi*hi
                }
        }
        __syncthreads();
    }

    // --- epilogue ---
    #pragma unroll
    for (int j = 0; j < 4; j++) {
        int col = warp_n * 32 + j * 8 + tig * 2;
        float2 bv = *reinterpret_cast<const float2*>(bias + col);
        #pragma unroll
        for (int i = 0; i < 2; i++) {
            int rbase = row0 + warp_m * 32 + i * 16 + grp;
            #pragma unroll
            for (int half = 0; half < 2; half++) {
                int r = rbase + half * 8;
                if (r >= M) continue;
                float2 v;
                v.x = acc[i][j][half * 2 + 0] + bv.x;
                v.y = acc[i][j][half * 2 + 1] + bv.y;
                if (HAS_RES) {
                    float2 rr = *reinterpret_cast<const float2*>(res + (size_t)r * 128 + col);
                    v.x += rr.x; v.y += rr.y;
                }
                if (RELU) { v.x = fmaxf(v.x, 0.f); v.y = fmaxf(v.y, 0.f); }
                *reinterpret_cast<float2*>(out + (size_t)r * 128 + col) = v;
            }
        }
    }
}

// ---------------------------------------------------------------------------

extern "C" void kernel_launch(void* const* d_in, const int* in_sizes, int n_in,
                              void* d_out, int out_size)
{
    const float* x     = (const float*)d_in[0];
    const float* Wm    = (const float*)d_in[1];
    const float* bm    = (const float*)d_in[2];
    const float* Wn2s0 = (const float*)d_in[3];
    const float* bn2s0 = (const float*)d_in[4];
    const float* Ws2n0 = (const float*)d_in[5];
    const float* bs2n0 = (const float*)d_in[6];
    const float* Wn2s1 = (const float*)d_in[7];
    const float* bn2s1 = (const float*)d_in[8];
    const float* Ws2n1 = (const float*)d_in[9];
    const float* bs2n1 = (const float*)d_in[10];
    const int* nei = (const int*)d_in[11];   // (2, NE) int32
    const int* r0  = (const int*)d_in[12];
    const int* c0  = (const int*)d_in[13];
    const int* r1  = (const int*)d_in[14];
    const int* c1  = (const int*)d_in[15];
    float* out = (float*)d_out;

    float *agg, *h, *h1, *sub, *sub2;
    cudaGetSymbolAddress((void**)&agg,  g_agg);
    cudaGetSymbolAddress((void**)&h,    g_h);
    cudaGetSymbolAddress((void**)&h1,   g_h1);
    cudaGetSymbolAddress((void**)&sub,  g_sub);
    cudaGetSymbolAddress((void**)&sub2, g_sub2);

    const size_t NB_N = (size_t)NN * D * sizeof(float);
    const size_t NB_S = (size_t)NS * D * sizeof(float);
    const int GB_N = (NN + 63) / 64;   // 782
    const int GB_S = (NS + 63) / 64;   // 313
    const int SC_NE = (NE * 32 + 255) / 256;
    const int SC_ES = (ES * 32 + 255) / 256;

    // --- message_neighbor: agg = scatter_sum(x[src] -> dst); h = relu((x+agg)@Wm+bm)
    cudaMemsetAsync(agg, 0, NB_N);
    scatter_add_k<<<SC_NE, 256>>>(x, nei, nei + NE, agg, NE);
    gemm128_tc<true, true, false><<<GB_N, 256>>>(x, agg, Wm, bm, nullptr, h, NN);

    // --- level 0 ---
    cudaMemsetAsync(sub, 0, NB_S);
    scatter_add_k<<<SC_ES, 256>>>(h, r0, c0, sub, ES);
    gemm128_tc<false, false, false><<<GB_S, 256>>>(sub, nullptr, Wn2s0, bn2s0, nullptr, sub2, NS);
    cudaMemsetAsync(agg, 0, NB_N);   // reuse as msg
    scatter_add_k<<<SC_ES, 256>>>(sub2, c0, r0, agg, ES);
    gemm128_tc<false, false, true><<<GB_N, 256>>>(agg, nullptr, Ws2n0, bs2n0, h, h1, NN);

    // --- level 1 ---
    cudaMemsetAsync(sub, 0, NB_S);
    scatter_add_k<<<SC_ES, 256>>>(h1, r1, c1, sub, ES);
    gemm128_tc<false, false, false><<<GB_S, 256>>>(sub, nullptr, Wn2s1, bn2s1, nullptr, sub2, NS);
    cudaMemsetAsync(agg, 0, NB_N);
    scatter_add_k<<<SC_ES, 256>>>(sub2, c1, r1, agg, ES);
    gemm128_tc<false, false, true><<<GB_N, 256>>>(agg, nullptr, Ws2n1, bs2n1, h1, out, NN);
}

// round 4
// speedup vs baseline: 2.0634x; 2.0634x over previous
#include <cuda_runtime.h>
#include <cuda_fp16.h>
#include <cuda_bf16.h>

#define D 128
#define NN 50000
#define NS 20000
#define NE 600000
#define ES 120000

__device__ float g_agg[(size_t)NN * D];
__device__ float g_h  [(size_t)NN * D];
__device__ float g_h1 [(size_t)NN * D];
__device__ float g_sub [(size_t)NS * D];
__device__ float g_sub2[(size_t)NS * D];

// ---------------------------------------------------------------------------
// Edge scatter: out[sidx[e]] += feat[gidx[e]]   (warp per edge, v4 reductions)
// ---------------------------------------------------------------------------
__global__ void scatter_add_k(const float* __restrict__ feat,
                              const int* __restrict__ gidx,
                              const int* __restrict__ sidx,
                              float* __restrict__ out, int nE)
{
    int t = blockIdx.x * blockDim.x + threadIdx.x;
    int e = t >> 5;
    int lane = t & 31;
    if (e >= nE) return;
    int g = gidx[e];
    int s = sidx[e];
    float4 v = reinterpret_cast<const float4*>(feat + (size_t)g * D)[lane];
    float* dst = out + (size_t)s * D + lane * 4;
    asm volatile("red.global.add.v4.f32 [%0], {%1,%2,%3,%4};"
                 :: "l"(dst), "f"(v.x), "f"(v.y), "f"(v.z), "f"(v.w)
                 : "memory");
}

// ---------------------------------------------------------------------------
// fp16x3 tensor GEMM: y[M,128] = epi( (A (+A2)) @ W + bias (+res) )
// Block 64x128, 8 warps (2x4), warp tile 32x32, mma.m16n8k16.f16.
// x = hi + lo (both fp16); acc += hi*hi + hi*lo + lo*hi  (err ~2^-24)
// Smem (dynamic, 104448B): As [64][68] u32 (m-major, kwords), hi+lo
//                          Ws [64][136] u32 (kword-major, n), hi+lo
// Fragment LDS bank-conflict-free by stride choice (68: 4g+t; 136: 8t+g).
// ---------------------------------------------------------------------------
#define AS_STRIDE 68
#define WS_STRIDE 136
#define AS_WORDS  (64 * AS_STRIDE)              // 4352
#define WS_WORDS  (64 * WS_STRIDE)              // 8704
#define SMEM_BYTES ((2 * AS_WORDS + 2 * WS_WORDS) * 4)   // 104448

__device__ __forceinline__ unsigned pack_split(float x0, float x1, unsigned& lo)
{
    __half h0 = __float2half_rn(x0), h1 = __float2half_rn(x1);
    __half l0 = __float2half_rn(x0 - __half2float(h0));
    __half l1 = __float2half_rn(x1 - __half2float(h1));
    __half2 lv = __halves2half2(l0, l1);
    __half2 hv = __halves2half2(h0, h1);
    lo = *reinterpret_cast<unsigned*>(&lv);
    return *reinterpret_cast<unsigned*>(&hv);
}

__device__ __forceinline__ void mma16(float c[4], const unsigned a[4], const unsigned b[2])
{
    asm volatile(
        "mma.sync.aligned.m16n8k16.row.col.f32.f16.f16.f32 "
        "{%0,%1,%2,%3}, {%4,%5,%6,%7}, {%8,%9}, {%0,%1,%2,%3};"
        : "+f"(c[0]), "+f"(c[1]), "+f"(c[2]), "+f"(c[3])
        : "r"(a[0]), "r"(a[1]), "r"(a[2]), "r"(a[3]), "r"(b[0]), "r"(b[1]));
}

template<bool RELU, bool HAS_IN2, bool HAS_RES>
__global__ __launch_bounds__(256)
void gemm128_h3(const float* __restrict__ A, const float* __restrict__ A2,
                const float* __restrict__ W, const float* __restrict__ bias,
                const float* __restrict__ res, float* __restrict__ out, int M)
{
    extern __shared__ unsigned sm[];
    unsigned* As_hi = sm;
    unsigned* As_lo = sm + AS_WORDS;
    unsigned* Ws_hi = sm + 2 * AS_WORDS;
    unsigned* Ws_lo = sm + 2 * AS_WORDS + WS_WORDS;

    const int tid    = threadIdx.x;
    const int lane   = tid & 31;
    const int wid    = tid >> 5;
    const int warp_m = wid & 1;
    const int warp_n = wid >> 1;
    const int grp    = lane >> 2;   // 0..7
    const int tig    = lane & 3;    // 0..3
    const int row0   = blockIdx.x * 64;

    // --- stage A (64 x 128 fp32 -> split fp16 pairs), m-major kwords ---
    #pragma unroll
    for (int h = 0; h < 8; h++) {
        int e = tid * 4 + h * 1024;
        int r = e >> 7, k = e & 127;
        int grow = row0 + r;
        float4 v = make_float4(0.f, 0.f, 0.f, 0.f);
        if (grow < M) {
            v = *reinterpret_cast<const float4*>(A + (size_t)grow * 128 + k);
            if (HAS_IN2) {
                float4 u = *reinterpret_cast<const float4*>(A2 + (size_t)grow * 128 + k);
                v.x += u.x; v.y += u.y; v.z += u.z; v.w += u.w;
            }
        }
        unsigned lo0, lo1;
        unsigned hi0 = pack_split(v.x, v.y, lo0);
        unsigned hi1 = pack_split(v.z, v.w, lo1);
        int base = r * AS_STRIDE + (k >> 1);
        *reinterpret_cast<uint2*>(&As_hi[base]) = make_uint2(hi0, hi1);
        *reinterpret_cast<uint2*>(&As_lo[base]) = make_uint2(lo0, lo1);
    }
    // --- stage W (128 x 128 fp32 -> split fp16 pairs), kword-major ---
    #pragma unroll 4
    for (int i = 0; i < 32; i++) {
        int e = tid + i * 256;
        int n = e & 127;
        int kw = e >> 7;            // 0..63
        float w0 = W[(size_t)(2 * kw)     * 128 + n];
        float w1 = W[(size_t)(2 * kw + 1) * 128 + n];
        unsigned lo;
        unsigned hi = pack_split(w0, w1, lo);
        Ws_hi[kw * WS_STRIDE + n] = hi;
        Ws_lo[kw * WS_STRIDE + n] = lo;
    }
    __syncthreads();

    float acc[2][4][4];
    #pragma unroll
    for (int i = 0; i < 2; i++)
        #pragma unroll
        for (int j = 0; j < 4; j++)
            #pragma unroll
            for (int c = 0; c < 4; c++) acc[i][j][c] = 0.f;

    #pragma unroll
    for (int kw0 = 0; kw0 < 64; kw0 += 8) {     // 8 k16 chunks
        unsigned ah[2][4], al[2][4];
        #pragma unroll
        for (int i = 0; i < 2; i++) {
            int r = warp_m * 32 + i * 16 + grp;
            int b0 = r * AS_STRIDE + kw0 + tig;
            int b8 = (r + 8) * AS_STRIDE + kw0 + tig;
            ah[i][0] = As_hi[b0];     al[i][0] = As_lo[b0];
            ah[i][1] = As_hi[b8];     al[i][1] = As_lo[b8];
            ah[i][2] = As_hi[b0 + 4]; al[i][2] = As_lo[b0 + 4];
            ah[i][3] = As_hi[b8 + 4]; al[i][3] = As_lo[b8 + 4];
        }
        unsigned bh[4][2], bl[4][2];
        #pragma unroll
        for (int j = 0; j < 4; j++) {
            int n = warp_n * 32 + j * 8 + grp;
            int t0 = (kw0 + tig) * WS_STRIDE + n;
            int t4 = (kw0 + tig + 4) * WS_STRIDE + n;
            bh[j][0] = Ws_hi[t0];  bl[j][0] = Ws_lo[t0];
            bh[j][1] = Ws_hi[t4];  bl[j][1] = Ws_lo[t4];
        }
        #pragma unroll
        for (int i = 0; i < 2; i++)
            #pragma unroll
            for (int j = 0; j < 4; j++) {
                mma16(acc[i][j], ah[i], bh[j]);
                mma16(acc[i][j], ah[i], bl[j]);
                mma16(acc[i][j], al[i], bh[j]);
            }
    }

    // --- epilogue ---
    #pragma unroll
    for (int j = 0; j < 4; j++) {
        int col = warp_n * 32 + j * 8 + tig * 2;
        float2 bv = *reinterpret_cast<const float2*>(bias + col);
        #pragma unroll
        for (int i = 0; i < 2; i++) {
            int rbase = row0 + warp_m * 32 + i * 16 + grp;
            #pragma unroll
            for (int half = 0; half < 2; half++) {
                int r = rbase + half * 8;
                if (r >= M) continue;
                float2 v;
                v.x = acc[i][j][half * 2 + 0] + bv.x;
                v.y = acc[i][j][half * 2 + 1] + bv.y;
                if (HAS_RES) {
                    float2 rr = *reinterpret_cast<const float2*>(res + (size_t)r * 128 + col);
                    v.x += rr.x; v.y += rr.y;
                }
                if (RELU) { v.x = fmaxf(v.x, 0.f); v.y = fmaxf(v.y, 0.f); }
                *reinterpret_cast<float2*>(out + (size_t)r * 128 + col) = v;
            }
        }
    }
}

// ---------------------------------------------------------------------------

extern "C" void kernel_launch(void* const* d_in, const int* in_sizes, int n_in,
                              void* d_out, int out_size)
{
    const float* x     = (const float*)d_in[0];
    const float* Wm    = (const float*)d_in[1];
    const float* bm    = (const float*)d_in[2];
    const float* Wn2s0 = (const float*)d_in[3];
    const float* bn2s0 = (const float*)d_in[4];
    const float* Ws2n0 = (const float*)d_in[5];
    const float* bs2n0 = (const float*)d_in[6];
    const float* Wn2s1 = (const float*)d_in[7];
    const float* bn2s1 = (const float*)d_in[8];
    const float* Ws2n1 = (const float*)d_in[9];
    const float* bs2n1 = (const float*)d_in[10];
    const int* nei = (const int*)d_in[11];
    const int* r0  = (const int*)d_in[12];
    const int* c0  = (const int*)d_in[13];
    const int* r1  = (const int*)d_in[14];
    const int* c1  = (const int*)d_in[15];
    float* out = (float*)d_out;

    float *agg, *h, *h1, *sub, *sub2;
    cudaGetSymbolAddress((void**)&agg,  g_agg);
    cudaGetSymbolAddress((void**)&h,    g_h);
    cudaGetSymbolAddress((void**)&h1,   g_h1);
    cudaGetSymbolAddress((void**)&sub,  g_sub);
    cudaGetSymbolAddress((void**)&sub2, g_sub2);

    cudaFuncSetAttribute(gemm128_h3<true,  true,  false>,
                         cudaFuncAttributeMaxDynamicSharedMemorySize, SMEM_BYTES);
    cudaFuncSetAttribute(gemm128_h3<false, false, false>,
                         cudaFuncAttributeMaxDynamicSharedMemorySize, SMEM_BYTES);
    cudaFuncSetAttribute(gemm128_h3<false, false, true>,
                         cudaFuncAttributeMaxDynamicSharedMemorySize, SMEM_BYTES);

    const size_t NB_N = (size_t)NN * D * sizeof(float);
    const size_t NB_S = (size_t)NS * D * sizeof(float);
    const int GB_N = (NN + 63) / 64;   // 782
    const int GB_S = (NS + 63) / 64;   // 313
    const int SC_NE = (NE * 32 + 255) / 256;
    const int SC_ES = (ES * 32 + 255) / 256;

    // --- message_neighbor ---
    cudaMemsetAsync(agg, 0, NB_N);
    scatter_add_k<<<SC_NE, 256>>>(x, nei, nei + NE, agg, NE);
    gemm128_h3<true, true, false><<<GB_N, 256, SMEM_BYTES>>>(x, agg, Wm, bm, nullptr, h, NN);

    // --- level 0 ---
    cudaMemsetAsync(sub, 0, NB_S);
    scatter_add_k<<<SC_ES, 256>>>(h, r0, c0, sub, ES);
    gemm128_h3<false, false, false><<<GB_S, 256, SMEM_BYTES>>>(sub, nullptr, Wn2s0, bn2s0, nullptr, sub2, NS);
    cudaMemsetAsync(agg, 0, NB_N);
    scatter_add_k<<<SC_ES, 256>>>(sub2, c0, r0, agg, ES);
    gemm128_h3<false, false, true><<<GB_N, 256, SMEM_BYTES>>>(agg, nullptr, Ws2n0, bs2n0, h, h1, NN);

    // --- level 1 ---
    cudaMemsetAsync(sub, 0, NB_S);
    scatter_add_k<<<SC_ES, 256>>>(h1, r1, c1, sub, ES);
    gemm128_h3<false, false, false><<<GB_S, 256, SMEM_BYTES>>>(sub, nullptr, Wn2s1, bn2s1, nullptr, sub2, NS);
    cudaMemsetAsync(agg, 0, NB_N);
    scatter_add_k<<<SC_ES, 256>>>(sub2, c1, r1, agg, ES);
    gemm128_h3<false, false, true><<<GB_N, 256, SMEM_BYTES>>>(agg, nullptr, Ws2n1, bs2n1, h1, out, NN);
}

// round 5
// speedup vs baseline: 2.3396x; 1.1339x over previous
#include <cuda_runtime.h>
#include <cuda_fp16.h>
#include <cuda_bf16.h>

#define D 128
#define NN 50000
#define NS 20000
#define NE 600000
#define ES 120000

__device__ float g_agg[(size_t)NN * D];
__device__ float g_h  [(size_t)NN * D];
__device__ float g_h1 [(size_t)NN * D];
__device__ float g_sub [(size_t)NS * D];
__device__ float g_sub2[(size_t)NS * D];

// Precomputed fp16 hi/lo splits of the 5 weight matrices, already in the
// padded [kw][WS_STRIDE] layout the GEMM wants in smem (bulk-copyable).
#define WS_STRIDE 136
#define WS_WORDS  (64 * WS_STRIDE)     // 8704 u32 per matrix per half
__device__ unsigned g_Whi[5 * WS_WORDS];
__device__ unsigned g_Wlo[5 * WS_WORDS];

// ---------------------------------------------------------------------------
// Edge scatter: out[sidx[e]] += feat[gidx[e]]   (warp per edge, v4 reductions)
// ---------------------------------------------------------------------------
__global__ void scatter_add_k(const float* __restrict__ feat,
                              const int* __restrict__ gidx,
                              const int* __restrict__ sidx,
                              float* __restrict__ out, int nE)
{
    int t = blockIdx.x * blockDim.x + threadIdx.x;
    int e = t >> 5;
    int lane = t & 31;
    if (e >= nE) return;
    int g = gidx[e];
    int s = sidx[e];
    float4 v = reinterpret_cast<const float4*>(feat + (size_t)g * D)[lane];
    float* dst = out + (size_t)s * D + lane * 4;
    asm volatile("red.global.add.v4.f32 [%0], {%1,%2,%3,%4};"
                 :: "l"(dst), "f"(v.x), "f"(v.y), "f"(v.z), "f"(v.w)
                 : "memory");
}

// ---------------------------------------------------------------------------
// fp16 split helpers
// ---------------------------------------------------------------------------
__device__ __forceinline__ unsigned pack_split(float x0, float x1, unsigned& lo)
{
    __half h0 = __float2half_rn(x0), h1 = __float2half_rn(x1);
    __half l0 = __float2half_rn(x0 - __half2float(h0));
    __half l1 = __float2half_rn(x1 - __half2float(h1));
    __half2 lv = __halves2half2(l0, l1);
    __half2 hv = __halves2half2(h0, h1);
    lo = *reinterpret_cast<unsigned*>(&lv);
    return *reinterpret_cast<unsigned*>(&hv);
}

// One-time W conversion: W fp32 [128k][128n] -> hi/lo half2 words [kw][136]
__global__ void convert_w_k(const float* W0, const float* W1, const float* W2,
                            const float* W3, const float* W4)
{
    const float* Ws[5] = {W0, W1, W2, W3, W4};
    const float* W = Ws[blockIdx.y];
    unsigned* dhi = g_Whi + blockIdx.y * WS_WORDS;
    unsigned* dlo = g_Wlo + blockIdx.y * WS_WORDS;
    int e = blockIdx.x * blockDim.x + threadIdx.x;   // 0..8191
    int kw = e >> 7, n = e & 127;
    float w0 = W[(size_t)(2 * kw)     * 128 + n];
    float w1 = W[(size_t)(2 * kw + 1) * 128 + n];
    unsigned lo;
    unsigned hi = pack_split(w0, w1, lo);
    dhi[kw * WS_STRIDE + n] = hi;
    dlo[kw * WS_STRIDE + n] = lo;
}

// ---------------------------------------------------------------------------
// fp16x3 tensor GEMM: y[M,128] = epi( (A (+A2)) @ W + bias (+res) )
// Block 64x128, 8 warps (2x4), warp tile 32x32, mma.m16n8k16.f16.
// W staged via cp.async from precomputed g_Whi/g_Wlo (bulk, non-blocking);
// A staged with load+split (A is dynamic). Fragment LDS conflict-free.
// ---------------------------------------------------------------------------
#define AS_STRIDE 68
#define AS_WORDS  (64 * AS_STRIDE)              // 4352
#define SMEM_BYTES ((2 * AS_WORDS + 2 * WS_WORDS) * 4)   // 104448

__device__ __forceinline__ void mma16(float c[4], const unsigned a[4], const unsigned b[2])
{
    asm volatile(
        "mma.sync.aligned.m16n8k16.row.col.f32.f16.f16.f32 "
        "{%0,%1,%2,%3}, {%4,%5,%6,%7}, {%8,%9}, {%0,%1,%2,%3};"
        : "+f"(c[0]), "+f"(c[1]), "+f"(c[2]), "+f"(c[3])
        : "r"(a[0]), "r"(a[1]), "r"(a[2]), "r"(a[3]), "r"(b[0]), "r"(b[1]));
}

template<bool RELU, bool HAS_IN2, bool HAS_RES>
__global__ __launch_bounds__(256, 2)
void gemm128_h3(const float* __restrict__ A, const float* __restrict__ A2,
                const unsigned* __restrict__ Whi, const unsigned* __restrict__ Wlo,
                const float* __restrict__ bias,
                const float* __restrict__ res, float* __restrict__ out, int M)
{
    extern __shared__ unsigned sm[];
    unsigned* As_hi = sm;
    unsigned* As_lo = sm + AS_WORDS;
    unsigned* Ws_hi = sm + 2 * AS_WORDS;
    unsigned* Ws_lo = sm + 2 * AS_WORDS + WS_WORDS;

    const int tid    = threadIdx.x;
    const int lane   = tid & 31;
    const int wid    = tid >> 5;
    const int warp_m = wid & 1;
    const int warp_n = wid >> 1;
    const int grp    = lane >> 2;   // 0..7
    const int tig    = lane & 3;    // 0..3
    const int row0   = blockIdx.x * 64;

    // --- W staging: bulk cp.async, 17 x 16B per thread (hi: 8.5 -> split 9+8) ---
    {
        unsigned shi = (unsigned)__cvta_generic_to_shared(Ws_hi);
        unsigned slo = (unsigned)__cvta_generic_to_shared(Ws_lo);
        // WS_WORDS*4 = 34816 B per half; 256 threads * 16B = 4096 B/iter -> 8.5 iters
        #pragma unroll
        for (int i = 0; i < 8; i++) {
            int off = (tid + i * 256) * 16;
            asm volatile("cp.async.cg.shared.global [%0], [%1], 16;"
                         :: "r"(shi + off), "l"((const char*)Whi + off));
            asm volatile("cp.async.cg.shared.global [%0], [%1], 16;"
                         :: "r"(slo + off), "l"((const char*)Wlo + off));
        }
        if (tid < 128) {   // remaining 2048 B of each half
            int off = 8 * 4096 + tid * 16;
            asm volatile("cp.async.cg.shared.global [%0], [%1], 16;"
                         :: "r"(shi + off), "l"((const char*)Whi + off));
            asm volatile("cp.async.cg.shared.global [%0], [%1], 16;"
                         :: "r"(slo + off), "l"((const char*)Wlo + off));
        }
        asm volatile("cp.async.commit_group;");
    }

    // --- stage A (64 x 128 fp32 -> split fp16 pairs), m-major kwords ---
    #pragma unroll
    for (int h = 0; h < 8; h++) {
        int e = tid * 4 + h * 1024;
        int r = e >> 7, k = e & 127;
        int grow = row0 + r;
        float4 v = make_float4(0.f, 0.f, 0.f, 0.f);
        if (grow < M) {
            v = *reinterpret_cast<const float4*>(A + (size_t)grow * 128 + k);
            if (HAS_IN2) {
                float4 u = *reinterpret_cast<const float4*>(A2 + (size_t)grow * 128 + k);
                v.x += u.x; v.y += u.y; v.z += u.z; v.w += u.w;
            }
        }
        unsigned lo0, lo1;
        unsigned hi0 = pack_split(v.x, v.y, lo0);
        unsigned hi1 = pack_split(v.z, v.w, lo1);
        int base = r * AS_STRIDE + (k >> 1);
        *reinterpret_cast<uint2*>(&As_hi[base]) = make_uint2(hi0, hi1);
        *reinterpret_cast<uint2*>(&As_lo[base]) = make_uint2(lo0, lo1);
    }

    asm volatile("cp.async.wait_group 0;");
    __syncthreads();

    float acc[2][4][4];
    #pragma unroll
    for (int i = 0; i < 2; i++)
        #pragma unroll
        for (int j = 0; j < 4; j++)
            #pragma unroll
            for (int c = 0; c < 4; c++) acc[i][j][c] = 0.f;

    #pragma unroll
    for (int kw0 = 0; kw0 < 64; kw0 += 8) {     // 8 k16 chunks
        unsigned ah[2][4], al[2][4];
        #pragma unroll
        for (int i = 0; i < 2; i++) {
            int r = warp_m * 32 + i * 16 + grp;
            int b0 = r * AS_STRIDE + kw0 + tig;
            int b8 = (r + 8) * AS_STRIDE + kw0 + tig;
            ah[i][0] = As_hi[b0];     al[i][0] = As_lo[b0];
            ah[i][1] = As_hi[b8];     al[i][1] = As_lo[b8];
            ah[i][2] = As_hi[b0 + 4]; al[i][2] = As_lo[b0 + 4];
            ah[i][3] = As_hi[b8 + 4]; al[i][3] = As_lo[b8 + 4];
        }
        unsigned bh[4][2], bl[4][2];
        #pragma unroll
        for (int j = 0; j < 4; j++) {
            int n = warp_n * 32 + j * 8 + grp;
            int t0 = (kw0 + tig) * WS_STRIDE + n;
            int t4 = (kw0 + tig + 4) * WS_STRIDE + n;
            bh[j][0] = Ws_hi[t0];  bl[j][0] = Ws_lo[t0];
            bh[j][1] = Ws_hi[t4];  bl[j][1] = Ws_lo[t4];
        }
        #pragma unroll
        for (int i = 0; i < 2; i++)
            #pragma unroll
            for (int j = 0; j < 4; j++) {
                mma16(acc[i][j], ah[i], bh[j]);
                mma16(acc[i][j], ah[i], bl[j]);
                mma16(acc[i][j], al[i], bh[j]);
            }
    }

    // --- epilogue ---
    #pragma unroll
    for (int j = 0; j < 4; j++) {
        int col = warp_n * 32 + j * 8 + tig * 2;
        float2 bv = *reinterpret_cast<const float2*>(bias + col);
        #pragma unroll
        for (int i = 0; i < 2; i++) {
            int rbase = row0 + warp_m * 32 + i * 16 + grp;
            #pragma unroll
            for (int half = 0; half < 2; half++) {
                int r = rbase + half * 8;
                if (r >= M) continue;
                float2 v;
                v.x = acc[i][j][half * 2 + 0] + bv.x;
                v.y = acc[i][j][half * 2 + 1] + bv.y;
                if (HAS_RES) {
                    float2 rr = *reinterpret_cast<const float2*>(res + (size_t)r * 128 + col);
                    v.x += rr.x; v.y += rr.y;
                }
                if (RELU) { v.x = fmaxf(v.x, 0.f); v.y = fmaxf(v.y, 0.f); }
                *reinterpret_cast<float2*>(out + (size_t)r * 128 + col) = v;
            }
        }
    }
}

// ---------------------------------------------------------------------------

extern "C" void kernel_launch(void* const* d_in, const int* in_sizes, int n_in,
                              void* d_out, int out_size)
{
    const float* x     = (const float*)d_in[0];
    const float* Wm    = (const float*)d_in[1];
    const float* bm    = (const float*)d_in[2];
    const float* Wn2s0 = (const float*)d_in[3];
    const float* bn2s0 = (const float*)d_in[4];
    const float* Ws2n0 = (const float*)d_in[5];
    const float* bs2n0 = (const float*)d_in[6];
    const float* Wn2s1 = (const float*)d_in[7];
    const float* bn2s1 = (const float*)d_in[8];
    const float* Ws2n1 = (const float*)d_in[9];
    const float* bs2n1 = (const float*)d_in[10];
    const int* nei = (const int*)d_in[11];
    const int* r0  = (const int*)d_in[12];
    const int* c0  = (const int*)d_in[13];
    const int* r1  = (const int*)d_in[14];
    const int* c1  = (const int*)d_in[15];
    float* out = (float*)d_out;

    float *agg, *h, *h1, *sub, *sub2;
    unsigned *whi, *wlo;
    cudaGetSymbolAddress((void**)&agg,  g_agg);
    cudaGetSymbolAddress((void**)&h,    g_h);
    cudaGetSymbolAddress((void**)&h1,   g_h1);
    cudaGetSymbolAddress((void**)&sub,  g_sub);
    cudaGetSymbolAddress((void**)&sub2, g_sub2);
    cudaGetSymbolAddress((void**)&whi,  g_Whi);
    cudaGetSymbolAddress((void**)&wlo,  g_Wlo);

    cudaFuncSetAttribute(gemm128_h3<true,  true,  false>,
                         cudaFuncAttributeMaxDynamicSharedMemorySize, SMEM_BYTES);
    cudaFuncSetAttribute(gemm128_h3<false, false, false>,
                         cudaFuncAttributeMaxDynamicSharedMemorySize, SMEM_BYTES);
    cudaFuncSetAttribute(gemm128_h3<false, false, true>,
                         cudaFuncAttributeMaxDynamicSharedMemorySize, SMEM_BYTES);

    const size_t NB_N = (size_t)NN * D * sizeof(float);
    const size_t NB_S = (size_t)NS * D * sizeof(float);
    const int GB_N = (NN + 63) / 64;   // 782
    const int GB_S = (NS + 63) / 64;   // 313
    const int SC_NE = (NE * 32 + 255) / 256;
    const int SC_ES = (ES * 32 + 255) / 256;

    // W index order: 0=Wm, 1=Wn2s0, 2=Ws2n0, 3=Wn2s1, 4=Ws2n1
    convert_w_k<<<dim3(32, 5), 256>>>(Wm, Wn2s0, Ws2n0, Wn2s1, Ws2n1);

    // --- message_neighbor ---
    cudaMemsetAsync(agg, 0, NB_N);
    scatter_add_k<<<SC_NE, 256>>>(x, nei, nei + NE, agg, NE);
    gemm128_h3<true, true, false><<<GB_N, 256, SMEM_BYTES>>>(
        x, agg, whi + 0 * WS_WORDS, wlo + 0 * WS_WORDS, bm, nullptr, h, NN);

    // --- level 0 ---
    cudaMemsetAsync(sub, 0, NB_S);
    scatter_add_k<<<SC_ES, 256>>>(h, r0, c0, sub, ES);
    gemm128_h3<false, false, false><<<GB_S, 256, SMEM_BYTES>>>(
        sub, nullptr, whi + 1 * WS_WORDS, wlo + 1 * WS_WORDS, bn2s0, nullptr, sub2, NS);
    cudaMemsetAsync(agg, 0, NB_N);
    scatter_add_k<<<SC_ES, 256>>>(sub2, c0, r0, agg, ES);
    gemm128_h3<false, false, true><<<GB_N, 256, SMEM_BYTES>>>(
        agg, nullptr, whi + 2 * WS_WORDS, wlo + 2 * WS_WORDS, bs2n0, h, h1, NN);

    // --- level 1 ---
    cudaMemsetAsync(sub, 0, NB_S);
    scatter_add_k<<<SC_ES, 256>>>(h1, r1, c1, sub, ES);
    gemm128_h3<false, false, false><<<GB_S, 256, SMEM_BYTES>>>(
        sub, nullptr, whi + 3 * WS_WORDS, wlo + 3 * WS_WORDS, bn2s1, nullptr, sub2, NS);
    cudaMemsetAsync(agg, 0, NB_N);
    scatter_add_k<<<SC_ES, 256>>>(sub2, c1, r1, agg, ES);
    gemm128_h3<false, false, true><<<GB_N, 256, SMEM_BYTES>>>(
        agg, nullptr, whi + 4 * WS_WORDS, wlo + 4 * WS_WORDS, bs2n1, h1, out, NN);
}

// round 6
// speedup vs baseline: 2.7159x; 1.1608x over previous
#include <cuda_runtime.h>
#include <cuda_fp16.h>
#include <cuda_bf16.h>

#define D 128
#define NN 50000
#define NS 20000
#define NE 600000
#define ES 120000
#define CAP 64
#define OVF_CAP 4096

__device__ float g_agg[(size_t)NN * D];
__device__ float g_h  [(size_t)NN * D];
__device__ float g_h1 [(size_t)NN * D];
__device__ float g_sub [(size_t)NS * D];
__device__ float g_sub2[(size_t)NS * D];

// CSR-bucket scratch (reused across all 5 reduction phases)
__device__ int g_cnt[NN];
__device__ int g_slot[(size_t)NN * CAP];
__device__ int g_ovfn;
__device__ int g_ovf[OVF_CAP * 2];

// Precomputed fp16 hi/lo splits of the 5 weight matrices (smem layout)
#define WS_STRIDE 136
#define WS_WORDS  (64 * WS_STRIDE)
__device__ unsigned g_Whi[5 * WS_WORDS];
__device__ unsigned g_Wlo[5 * WS_WORDS];

// ---------------------------------------------------------------------------
// CSR bucket build
// ---------------------------------------------------------------------------
__global__ void zero_cnt_k(int n)
{
    int i = blockIdx.x * blockDim.x + threadIdx.x;
    if (i < n) g_cnt[i] = 0;
    if (i == 0) g_ovfn = 0;
}

__global__ void fill_k(const int* __restrict__ gidx,   // gather (source row)
                       const int* __restrict__ sidx,   // segment (dest row)
                       int nE)
{
    int e = blockIdx.x * blockDim.x + threadIdx.x;
    if (e >= nE) return;
    int s = sidx[e];
    int p = atomicAdd(&g_cnt[s], 1);
    if (p < CAP) {
        g_slot[(size_t)s * CAP + p] = gidx[e];
    } else {
        int o = atomicAdd(&g_ovfn, 1);
        if (o < OVF_CAP) { g_ovf[2 * o] = gidx[e]; g_ovf[2 * o + 1] = s; }
    }
}

// Warp per node: out[n] = sum_{j<deg} feat[slot[n][j]]  (plain store, no memset)
__global__ void reduce_k(const float* __restrict__ feat,
                         float* __restrict__ out, int nNodes)
{
    int t = blockIdx.x * blockDim.x + threadIdx.x;
    int w = t >> 5, lane = t & 31;
    if (w >= nNodes) return;
    int deg = g_cnt[w];
    if (deg > CAP) deg = CAP;
    const int* sl = g_slot + (size_t)w * CAP;
    float4 a0 = make_float4(0.f, 0.f, 0.f, 0.f), a1 = a0, a2 = a0, a3 = a0;
    int j = 0;
    for (; j + 4 <= deg; j += 4) {
        int s0 = sl[j], s1 = sl[j + 1], s2 = sl[j + 2], s3 = sl[j + 3];
        float4 v0 = reinterpret_cast<const float4*>(feat + (size_t)s0 * D)[lane];
        float4 v1 = reinterpret_cast<const float4*>(feat + (size_t)s1 * D)[lane];
        float4 v2 = reinterpret_cast<const float4*>(feat + (size_t)s2 * D)[lane];
        float4 v3 = reinterpret_cast<const float4*>(feat + (size_t)s3 * D)[lane];
        a0.x += v0.x; a0.y += v0.y; a0.z += v0.z; a0.w += v0.w;
        a1.x += v1.x; a1.y += v1.y; a1.z += v1.z; a1.w += v1.w;
        a2.x += v2.x; a2.y += v2.y; a2.z += v2.z; a2.w += v2.w;
        a3.x += v3.x; a3.y += v3.y; a3.z += v3.z; a3.w += v3.w;
    }
    for (; j < deg; j++) {
        float4 v = reinterpret_cast<const float4*>(feat + (size_t)sl[j] * D)[lane];
        a0.x += v.x; a0.y += v.y; a0.z += v.z; a0.w += v.w;
    }
    float4 r;
    r.x = (a0.x + a1.x) + (a2.x + a3.x);
    r.y = (a0.y + a1.y) + (a2.y + a3.y);
    r.z = (a0.z + a1.z) + (a2.z + a3.z);
    r.w = (a0.w + a1.w) + (a2.w + a3.w);
    reinterpret_cast<float4*>(out + (size_t)w * D)[lane] = r;
}

// Overflow cleanup (normally 0 edges): warp per overflow edge, red.global
__global__ void ovf_k(const float* __restrict__ feat, float* __restrict__ out)
{
    int t = blockIdx.x * blockDim.x + threadIdx.x;
    int w = t >> 5, lane = t & 31;
    int n = g_ovfn; if (n > OVF_CAP) n = OVF_CAP;
    if (w >= n) return;
    int g = g_ovf[2 * w], s = g_ovf[2 * w + 1];
    float4 v = reinterpret_cast<const float4*>(feat + (size_t)g * D)[lane];
    float* dst = out + (size_t)s * D + lane * 4;
    asm volatile("red.global.add.v4.f32 [%0], {%1,%2,%3,%4};"
                 :: "l"(dst), "f"(v.x), "f"(v.y), "f"(v.z), "f"(v.w)
                 : "memory");
}

// ---------------------------------------------------------------------------
// fp16 split helpers + one-time W conversion
// ---------------------------------------------------------------------------
__device__ __forceinline__ unsigned pack_split(float x0, float x1, unsigned& lo)
{
    __half h0 = __float2half_rn(x0), h1 = __float2half_rn(x1);
    __half l0 = __float2half_rn(x0 - __half2float(h0));
    __half l1 = __float2half_rn(x1 - __half2float(h1));
    __half2 lv = __halves2half2(l0, l1);
    __half2 hv = __halves2half2(h0, h1);
    lo = *reinterpret_cast<unsigned*>(&lv);
    return *reinterpret_cast<unsigned*>(&hv);
}

__global__ void convert_w_k(const float* W0, const float* W1, const float* W2,
                            const float* W3, const float* W4)
{
    const float* Ws[5] = {W0, W1, W2, W3, W4};
    const float* W = Ws[blockIdx.y];
    unsigned* dhi = g_Whi + blockIdx.y * WS_WORDS;
    unsigned* dlo = g_Wlo + blockIdx.y * WS_WORDS;
    int e = blockIdx.x * blockDim.x + threadIdx.x;
    int kw = e >> 7, n = e & 127;
    float w0 = W[(size_t)(2 * kw)     * 128 + n];
    float w1 = W[(size_t)(2 * kw + 1) * 128 + n];
    unsigned lo;
    unsigned hi = pack_split(w0, w1, lo);
    dhi[kw * WS_STRIDE + n] = hi;
    dlo[kw * WS_STRIDE + n] = lo;
}

// ---------------------------------------------------------------------------
// fp16x3 tensor GEMM (as R5): y[M,128] = epi( (A (+A2)) @ W + bias (+res) )
// ---------------------------------------------------------------------------
#define AS_STRIDE 68
#define AS_WORDS  (64 * AS_STRIDE)
#define SMEM_BYTES ((2 * AS_WORDS + 2 * WS_WORDS) * 4)

__device__ __forceinline__ void mma16(float c[4], const unsigned a[4], const unsigned b[2])
{
    asm volatile(
        "mma.sync.aligned.m16n8k16.row.col.f32.f16.f16.f32 "
        "{%0,%1,%2,%3}, {%4,%5,%6,%7}, {%8,%9}, {%0,%1,%2,%3};"
        : "+f"(c[0]), "+f"(c[1]), "+f"(c[2]), "+f"(c[3])
        : "r"(a[0]), "r"(a[1]), "r"(a[2]), "r"(a[3]), "r"(b[0]), "r"(b[1]));
}

template<bool RELU, bool HAS_IN2, bool HAS_RES>
__global__ __launch_bounds__(256, 2)
void gemm128_h3(const float* __restrict__ A, const float* __restrict__ A2,
                const unsigned* __restrict__ Whi, const unsigned* __restrict__ Wlo,
                const float* __restrict__ bias,
                const float* __restrict__ res, float* __restrict__ out, int M)
{
    extern __shared__ unsigned sm[];
    unsigned* As_hi = sm;
    unsigned* As_lo = sm + AS_WORDS;
    unsigned* Ws_hi = sm + 2 * AS_WORDS;
    unsigned* Ws_lo = sm + 2 * AS_WORDS + WS_WORDS;

    const int tid    = threadIdx.x;
    const int lane   = tid & 31;
    const int wid    = tid >> 5;
    const int warp_m = wid & 1;
    const int warp_n = wid >> 1;
    const int grp    = lane >> 2;
    const int tig    = lane & 3;
    const int row0   = blockIdx.x * 64;

    // W staging via cp.async (bulk copy, layout-identical)
    {
        unsigned shi = (unsigned)__cvta_generic_to_shared(Ws_hi);
        unsigned slo = (unsigned)__cvta_generic_to_shared(Ws_lo);
        #pragma unroll
        for (int i = 0; i < 8; i++) {
            int off = (tid + i * 256) * 16;
            asm volatile("cp.async.cg.shared.global [%0], [%1], 16;"
                         :: "r"(shi + off), "l"((const char*)Whi + off));
            asm volatile("cp.async.cg.shared.global [%0], [%1], 16;"
                         :: "r"(slo + off), "l"((const char*)Wlo + off));
        }
        if (tid < 128) {
            int off = 8 * 4096 + tid * 16;
            asm volatile("cp.async.cg.shared.global [%0], [%1], 16;"
                         :: "r"(shi + off), "l"((const char*)Whi + off));
            asm volatile("cp.async.cg.shared.global [%0], [%1], 16;"
                         :: "r"(slo + off), "l"((const char*)Wlo + off));
        }
        asm volatile("cp.async.commit_group;");
    }

    // A staging: load fp32 (+A2), split to fp16 hi/lo
    #pragma unroll
    for (int h = 0; h < 8; h++) {
        int e = tid * 4 + h * 1024;
        int r = e >> 7, k = e & 127;
        int grow = row0 + r;
        float4 v = make_float4(0.f, 0.f, 0.f, 0.f);
        if (grow < M) {
            v = *reinterpret_cast<const float4*>(A + (size_t)grow * 128 + k);
            if (HAS_IN2) {
                float4 u = *reinterpret_cast<const float4*>(A2 + (size_t)grow * 128 + k);
                v.x += u.x; v.y += u.y; v.z += u.z; v.w += u.w;
            }
        }
        unsigned lo0, lo1;
        unsigned hi0 = pack_split(v.x, v.y, lo0);
        unsigned hi1 = pack_split(v.z, v.w, lo1);
        int base = r * AS_STRIDE + (k >> 1);
        *reinterpret_cast<uint2*>(&As_hi[base]) = make_uint2(hi0, hi1);
        *reinterpret_cast<uint2*>(&As_lo[base]) = make_uint2(lo0, lo1);
    }

    asm volatile("cp.async.wait_group 0;");
    __syncthreads();

    float acc[2][4][4];
    #pragma unroll
    for (int i = 0; i < 2; i++)
        #pragma unroll
        for (int j = 0; j < 4; j++)
            #pragma unroll
            for (int c = 0; c < 4; c++) acc[i][j][c] = 0.f;

    #pragma unroll
    for (int kw0 = 0; kw0 < 64; kw0 += 8) {
        unsigned ah[2][4], al[2][4];
        #pragma unroll
        for (int i = 0; i < 2; i++) {
            int r = warp_m * 32 + i * 16 + grp;
            int b0 = r * AS_STRIDE + kw0 + tig;
            int b8 = (r + 8) * AS_STRIDE + kw0 + tig;
            ah[i][0] = As_hi[b0];     al[i][0] = As_lo[b0];
            ah[i][1] = As_hi[b8];     al[i][1] = As_lo[b8];
            ah[i][2] = As_hi[b0 + 4]; al[i][2] = As_lo[b0 + 4];
            ah[i][3] = As_hi[b8 + 4]; al[i][3] = As_lo[b8 + 4];
        }
        unsigned bh[4][2], bl[4][2];
        #pragma unroll
        for (int j = 0; j < 4; j++) {
            int n = warp_n * 32 + j * 8 + grp;
            int t0 = (kw0 + tig) * WS_STRIDE + n;
            int t4 = (kw0 + tig + 4) * WS_STRIDE + n;
            bh[j][0] = Ws_hi[t0];  bl[j][0] = Ws_lo[t0];
            bh[j][1] = Ws_hi[t4];  bl[j][1] = Ws_lo[t4];
        }
        #pragma unroll
        for (int i = 0; i < 2; i++)
            #pragma unroll
            for (int j = 0; j < 4; j++) {
                mma16(acc[i][j], ah[i], bh[j]);
                mma16(acc[i][j], ah[i], bl[j]);
                mma16(acc[i][j], al[i], bh[j]);
            }
    }

    #pragma unroll
    for (int j = 0; j < 4; j++) {
        int col = warp_n * 32 + j * 8 + tig * 2;
        float2 bv = *reinterpret_cast<const float2*>(bias + col);
        #pragma unroll
        for (int i = 0; i < 2; i++) {
            int rbase = row0 + warp_m * 32 + i * 16 + grp;
            #pragma unroll
            for (int half = 0; half < 2; half++) {
                int r = rbase + half * 8;
                if (r >= M) continue;
                float2 v;
                v.x = acc[i][j][half * 2 + 0] + bv.x;
                v.y = acc[i][j][half * 2 + 1] + bv.y;
                if (HAS_RES) {
                    float2 rr = *reinterpret_cast<const float2*>(res + (size_t)r * 128 + col);
                    v.x += rr.x; v.y += rr.y;
                }
                if (RELU) { v.x = fmaxf(v.x, 0.f); v.y = fmaxf(v.y, 0.f); }
                *reinterpret_cast<float2*>(out + (size_t)r * 128 + col) = v;
            }
        }
    }
}

// ---------------------------------------------------------------------------

extern "C" void kernel_launch(void* const* d_in, const int* in_sizes, int n_in,
                              void* d_out, int out_size)
{
    const float* x     = (const float*)d_in[0];
    const float* Wm    = (const float*)d_in[1];
    const float* bm    = (const float*)d_in[2];
    const float* Wn2s0 = (const float*)d_in[3];
    const float* bn2s0 = (const float*)d_in[4];
    const float* Ws2n0 = (const float*)d_in[5];
    const float* bs2n0 = (const float*)d_in[6];
    const float* Wn2s1 = (const float*)d_in[7];
    const float* bn2s1 = (const float*)d_in[8];
    const float* Ws2n1 = (const float*)d_in[9];
    const float* bs2n1 = (const float*)d_in[10];
    const int* nei = (const int*)d_in[11];
    const int* r0  = (const int*)d_in[12];
    const int* c0  = (const int*)d_in[13];
    const int* r1  = (const int*)d_in[14];
    const int* c1  = (const int*)d_in[15];
    float* out = (float*)d_out;

    float *agg, *h, *h1, *sub, *sub2;
    unsigned *whi, *wlo;
    cudaGetSymbolAddress((void**)&agg,  g_agg);
    cudaGetSymbolAddress((void**)&h,    g_h);
    cudaGetSymbolAddress((void**)&h1,   g_h1);
    cudaGetSymbolAddress((void**)&sub,  g_sub);
    cudaGetSymbolAddress((void**)&sub2, g_sub2);
    cudaGetSymbolAddress((void**)&whi,  g_Whi);
    cudaGetSymbolAddress((void**)&wlo,  g_Wlo);

    cudaFuncSetAttribute(gemm128_h3<true,  true,  false>,
                         cudaFuncAttributeMaxDynamicSharedMemorySize, SMEM_BYTES);
    cudaFuncSetAttribute(gemm128_h3<false, false, false>,
                         cudaFuncAttributeMaxDynamicSharedMemorySize, SMEM_BYTES);
    cudaFuncSetAttribute(gemm128_h3<false, false, true>,
                         cudaFuncAttributeMaxDynamicSharedMemorySize, SMEM_BYTES);

    const int GB_N = (NN + 63) / 64;
    const int GB_S = (NS + 63) / 64;
    const int ZB_N = (NN + 255) / 256;
    const int ZB_S = (NS + 255) / 256;
    const int FB_NE = (NE + 255) / 256;
    const int FB_ES = (ES + 255) / 256;
    const int RB_N = (NN * 32 + 255) / 256;
    const int RB_S = (NS * 32 + 255) / 256;
    const int OB   = (OVF_CAP * 32 + 255) / 256;

    convert_w_k<<<dim3(32, 5), 256>>>(Wm, Wn2s0, Ws2n0, Wn2s1, Ws2n1);

    // --- message_neighbor: agg = segsum(x[src]->dst); h = relu((x+agg)@Wm+bm)
    zero_cnt_k<<<ZB_N, 256>>>(NN);
    fill_k<<<FB_NE, 256>>>(nei, nei + NE, NE);
    reduce_k<<<RB_N, 256>>>(x, agg, NN);
    ovf_k<<<OB, 256>>>(x, agg);
    gemm128_h3<true, true, false><<<GB_N, 256, SMEM_BYTES>>>(
        x, agg, whi + 0 * WS_WORDS, wlo + 0 * WS_WORDS, bm, nullptr, h, NN);

    // --- level 0 ---
    zero_cnt_k<<<ZB_S, 256>>>(NS);
    fill_k<<<FB_ES, 256>>>(r0, c0, ES);
    reduce_k<<<RB_S, 256>>>(h, sub, NS);
    ovf_k<<<OB, 256>>>(h, sub);
    gemm128_h3<false, false, false><<<GB_S, 256, SMEM_BYTES>>>(
        sub, nullptr, whi + 1 * WS_WORDS, wlo + 1 * WS_WORDS, bn2s0, nullptr, sub2, NS);
    zero_cnt_k<<<ZB_N, 256>>>(NN);
    fill_k<<<FB_ES, 256>>>(c0, r0, ES);
    reduce_k<<<RB_N, 256>>>(sub2, agg, NN);
    ovf_k<<<OB, 256>>>(sub2, agg);
    gemm128_h3<false, false, true><<<GB_N, 256, SMEM_BYTES>>>(
        agg, nullptr, whi + 2 * WS_WORDS, wlo + 2 * WS_WORDS, bs2n0, h, h1, NN);

    // --- level 1 ---
    zero_cnt_k<<<ZB_S, 256>>>(NS);
    fill_k<<<FB_ES, 256>>>(r1, c1, ES);
    reduce_k<<<RB_S, 256>>>(h1, sub, NS);
    ovf_k<<<OB, 256>>>(h1, sub);
    gemm128_h3<false, false, false><<<GB_S, 256, SMEM_BYTES>>>(
        sub, nullptr, whi + 3 * WS_WORDS, wlo + 3 * WS_WORDS, bn2s1, nullptr, sub2, NS);
    zero_cnt_k<<<ZB_N, 256>>>(NN);
    fill_k<<<FB_ES, 256>>>(c1, r1, ES);
    reduce_k<<<RB_N, 256>>>(sub2, agg, NN);
    ovf_k<<<OB, 256>>>(sub2, agg);
    gemm128_h3<false, false, true><<<GB_N, 256, SMEM_BYTES>>>(
        agg, nullptr, whi + 4 * WS_WORDS, wlo + 4 * WS_WORDS, bs2n1, h1, out, NN);
}